// round 2
// baseline (speedup 1.0000x reference)
#include <cuda_runtime.h>
#include <math.h>

// GlobalAttentionPooling: per-segment softmax attention readout.
//   gate = feat @ W + b        [N,1]
//   alpha = segment_softmax(gate)
//   out[b] = sum_{n in seg b} alpha[n] * feat[n]    -> [B, D]
//
// Strategy: ONE streaming pass over feat using per-segment online softmax.
// segment_ids are sorted -> each segment is a contiguous row range.
// One CTA per segment, 256 threads (one per feature dim).

#define DD 256
#define MAXB 4096
#define CH 8

__device__ int g_seg_start[MAXB + 1];

// Compute segment start offsets. Handles empty segments (gaps) and both
// int64/int32 segment_ids via on-device dtype detection:
//  - int64 (little-endian, values < 2^31): int32 view index (n-1) [odd, n even]
//    is the HIGH word of an element -> 0.
//  - int32 sorted data: last element ~ B-1 != 0.
__global__ void seg_bounds_kernel(const int* __restrict__ seg32, int n, int nseg) {
    int stride = (seg32[n - 1] == 0) ? 2 : 1;
    int i = blockIdx.x * blockDim.x + threadIdx.x;
    if (i >= n) return;
    int s  = seg32[(size_t)i * stride];
    int sp = (i == 0) ? -1 : seg32[(size_t)(i - 1) * stride];
    for (int t = sp + 1; t <= s; ++t) g_seg_start[t] = i;
    if (i == n - 1) {
        for (int t = s + 1; t <= nseg; ++t) g_seg_start[t] = n;
    }
}

__global__ __launch_bounds__(DD) void pool_kernel(
    const float* __restrict__ feat,
    const float* __restrict__ Wg,
    const float* __restrict__ bg,
    float* __restrict__ out)
{
    const int b    = blockIdx.x;
    const int tid  = threadIdx.x;
    const int lane = tid & 31;
    const int warp = tid >> 5;

    const int start = g_seg_start[b];
    const int end   = g_seg_start[b + 1];

    const float w    = Wg[tid];
    const float bias = bg[0];

    __shared__ float s_part[CH][8];  // [chunk-node][warp] partial dots
    __shared__ float s_e[CH];        // exp(g_j - m_new), broadcast
    __shared__ float s_r;            // rescale factor exp(m_old - m_new)

    float acc  = 0.0f;              // running weighted feature (this thread's dim)
    float ssum = 0.0f;              // running sum of exp (uniform across threads)
    float m    = -INFINITY;         // running max (live only in warp0 lanes 0..7)

    for (int i = start; i < end; i += CH) {
        const int c = min(CH, end - i);

        // ---- load chunk + per-thread partial dot products (MLP = 8) ----
        float v[CH], p[CH];
        #pragma unroll
        for (int j = 0; j < CH; ++j) {
            v[j] = (j < c) ? feat[(size_t)(i + j) * DD + tid] : 0.0f;
            p[j] = v[j] * w;
        }

        // ---- warp-level reduce each of the 8 dots ----
        #pragma unroll
        for (int j = 0; j < CH; ++j) {
            #pragma unroll
            for (int off = 16; off > 0; off >>= 1)
                p[j] += __shfl_xor_sync(0xffffffffu, p[j], off);
        }
        if (lane == 0) {
            #pragma unroll
            for (int j = 0; j < CH; ++j) s_part[j][warp] = p[j];
        }
        __syncthreads();  // (B) partials visible; also protects prev-iter s_e reads

        // ---- warp0 lanes 0..7: finish dots, online-softmax scalars (few MUFU) ----
        if (warp == 0 && lane < CH) {
            float g = bias;
            #pragma unroll
            for (int wp = 0; wp < 8; ++wp) g += s_part[lane][wp];
            if (lane >= c) g = -INFINITY;      // pad lanes don't affect max
            // max over the 8 chunk gates (lanes 0..7)
            float cm = g;
            #pragma unroll
            for (int off = 4; off > 0; off >>= 1)
                cm = fmaxf(cm, __shfl_xor_sync(0x000000ffu, cm, off));
            const float newm = fmaxf(m, cm);
            const float r    = __expf(m - newm);   // first chunk: exp(-inf)=0
            const float e    = __expf(g - newm);   // pad lanes -> 0
            m = newm;
            s_e[lane] = e;
            if (lane == 0) s_r = r;
        }
        __syncthreads();  // (C) e/r visible to everyone

        // ---- all threads: pure FFMA update of running state ----
        const float r = s_r;
        acc  *= r;
        ssum *= r;
        #pragma unroll
        for (int j = 0; j < CH; ++j) {
            if (j < c) {
                const float e = s_e[j];
                acc  = fmaf(e, v[j], acc);
                ssum += e;
            }
        }
    }

    out[(size_t)b * DD + tid] = (end > start) ? (acc / ssum) : 0.0f;
}

extern "C" void kernel_launch(void* const* d_in, const int* in_sizes, int n_in,
                              void* d_out, int out_size) {
    const float* feat  = (const float*)d_in[0];
    const float* Wg    = (const float*)d_in[1];
    const float* bg    = (const float*)d_in[2];
    const int*   seg32 = (const int*)d_in[3];   // int32 view; dtype detected on device

    const int n    = in_sizes[0] / DD;          // number of nodes
    int nseg = out_size / DD;                   // number of segments
    if (nseg > MAXB) nseg = MAXB;

    seg_bounds_kernel<<<(n + 255) / 256, 256>>>(seg32, n, nseg);
    pool_kernel<<<nseg, DD>>>(feat, Wg, bg, (float*)d_out);
}

// round 3
// speedup vs baseline: 1.7655x; 1.7655x over previous
#include <cuda_runtime.h>
#include <math.h>

// GlobalAttentionPooling: per-segment softmax attention readout (single pass).
//   gate = feat @ W (+b, shift-invariant -> dropped)
//   alpha = segment_softmax(gate);  out[b] = sum alpha_n * feat_n
//
// Layout: one CTA (128 thr = 4 warps) per segment. Each warp owns every 4th
// node; lane l holds dims [4l..4l+3] and [128+4l..131+4l] via two LDG.128.
// Each warp runs an independent online softmax (m, ssum, acc[8]); the four
// warp states are softmax-merged through shared memory at the end.
// Mainloop has ZERO barriers and one 5-step butterfly per node.

#define DD 256
#define MAXB 4096
#define NW 4      // warps per CTA

__device__ int g_seg_start[MAXB + 1];

// Segment start offsets from sorted ids. Handles empty segments and both
// int64/int32 ids via on-device dtype detection: for little-endian int64
// (values < 2^31) the int32 view at odd index n-1 (n even) is a high word = 0;
// sorted int32 data has last id ~ B-1 != 0.
__global__ void seg_bounds_kernel(const int* __restrict__ seg32, int n, int nseg) {
    int stride = (seg32[n - 1] == 0) ? 2 : 1;
    int i = blockIdx.x * blockDim.x + threadIdx.x;
    if (i >= n) return;
    int s  = seg32[(size_t)i * stride];
    int sp = (i == 0) ? -1 : seg32[(size_t)(i - 1) * stride];
    for (int t = sp + 1; t <= s; ++t) g_seg_start[t] = i;
    if (i == n - 1) {
        for (int t = s + 1; t <= nseg; ++t) g_seg_start[t] = n;
    }
}

__global__ __launch_bounds__(NW * 32) void pool_kernel(
    const float* __restrict__ feat,
    const float* __restrict__ Wg,
    float* __restrict__ out)
{
    const int b    = blockIdx.x;
    const int tid  = threadIdx.x;
    const int lane = tid & 31;
    const int warp = tid >> 5;

    const int start = g_seg_start[b];
    const int end   = g_seg_start[b + 1];

    // Empty segment -> zeros (uniform early exit, before any barrier)
    if (start >= end) {
        out[(size_t)b * DD + tid]       = 0.0f;
        out[(size_t)b * DD + tid + 128] = 0.0f;
        return;
    }

    const float4* W4  = (const float4*)Wg;
    const float4 w_lo = W4[lane];
    const float4 w_hi = W4[lane + 32];

    float4 acc_lo = make_float4(0.f, 0.f, 0.f, 0.f);
    float4 acc_hi = make_float4(0.f, 0.f, 0.f, 0.f);
    float  m    = -INFINITY;
    float  ssum = 0.0f;

    for (int i = start + warp; i < end; i += NW) {
        const float4* row = (const float4*)(feat + (size_t)i * DD);
        const float4 v_lo = row[lane];
        const float4 v_hi = row[lane + 32];

        // gate dot-product: 8 FFMA + one 5-step butterfly (result in all lanes)
        float g;
        g = v_lo.x * w_lo.x;
        g = fmaf(v_lo.y, w_lo.y, g);
        g = fmaf(v_lo.z, w_lo.z, g);
        g = fmaf(v_lo.w, w_lo.w, g);
        g = fmaf(v_hi.x, w_hi.x, g);
        g = fmaf(v_hi.y, w_hi.y, g);
        g = fmaf(v_hi.z, w_hi.z, g);
        g = fmaf(v_hi.w, w_hi.w, g);
        #pragma unroll
        for (int off = 16; off > 0; off >>= 1)
            g += __shfl_xor_sync(0xffffffffu, g, off);

        if (g > m) {
            // new running max: rescale state (rare after warm-up), e = 1
            const float r = __expf(m - g);   // first node: exp(-inf) = 0
            m = g;
            ssum = fmaf(ssum, r, 1.0f);
            acc_lo.x = fmaf(acc_lo.x, r, v_lo.x);
            acc_lo.y = fmaf(acc_lo.y, r, v_lo.y);
            acc_lo.z = fmaf(acc_lo.z, r, v_lo.z);
            acc_lo.w = fmaf(acc_lo.w, r, v_lo.w);
            acc_hi.x = fmaf(acc_hi.x, r, v_hi.x);
            acc_hi.y = fmaf(acc_hi.y, r, v_hi.y);
            acc_hi.z = fmaf(acc_hi.z, r, v_hi.z);
            acc_hi.w = fmaf(acc_hi.w, r, v_hi.w);
        } else {
            // common path: no rescale
            const float e = __expf(g - m);
            ssum += e;
            acc_lo.x = fmaf(e, v_lo.x, acc_lo.x);
            acc_lo.y = fmaf(e, v_lo.y, acc_lo.y);
            acc_lo.z = fmaf(e, v_lo.z, acc_lo.z);
            acc_lo.w = fmaf(e, v_lo.w, acc_lo.w);
            acc_hi.x = fmaf(e, v_hi.x, acc_hi.x);
            acc_hi.y = fmaf(e, v_hi.y, acc_hi.y);
            acc_hi.z = fmaf(e, v_hi.z, acc_hi.z);
            acc_hi.w = fmaf(e, v_hi.w, acc_hi.w);
        }
    }

    // ---- merge the NW per-warp softmax states through shared memory ----
    __shared__ float s_m[NW];
    __shared__ float s_s[NW];
    __shared__ float s_acc[NW][DD];

    if (lane == 0) s_m[warp] = m;
    __syncthreads();

    float M = s_m[0];
    #pragma unroll
    for (int wv = 1; wv < NW; ++wv) M = fmaxf(M, s_m[wv]);

    // per-warp scale to the global max (warp with no nodes: m=-inf -> scale 0)
    const float scale = __expf(m - M);
    if (lane == 0) s_s[warp] = ssum * scale;

    float4* sa = (float4*)s_acc[warp];
    acc_lo.x *= scale; acc_lo.y *= scale; acc_lo.z *= scale; acc_lo.w *= scale;
    acc_hi.x *= scale; acc_hi.y *= scale; acc_hi.z *= scale; acc_hi.w *= scale;
    sa[lane]      = acc_lo;
    sa[lane + 32] = acc_hi;
    __syncthreads();

    float tot = s_s[0];
    #pragma unroll
    for (int wv = 1; wv < NW; ++wv) tot += s_s[wv];
    const float inv = 1.0f / tot;

    // each thread writes dims tid and tid+128
    float o0 = 0.f, o1 = 0.f;
    #pragma unroll
    for (int wv = 0; wv < NW; ++wv) {
        o0 += s_acc[wv][tid];
        o1 += s_acc[wv][tid + 128];
    }
    out[(size_t)b * DD + tid]       = o0 * inv;
    out[(size_t)b * DD + tid + 128] = o1 * inv;
}

extern "C" void kernel_launch(void* const* d_in, const int* in_sizes, int n_in,
                              void* d_out, int out_size) {
    const float* feat  = (const float*)d_in[0];
    const float* Wg    = (const float*)d_in[1];
    const int*   seg32 = (const int*)d_in[3];   // int32 view; dtype detected on device

    const int n = in_sizes[0] / DD;
    int nseg = out_size / DD;
    if (nseg > MAXB) nseg = MAXB;

    seg_bounds_kernel<<<(n + 255) / 256, 256>>>(seg32, n, nseg);
    pool_kernel<<<nseg, NW * 32>>>(feat, Wg, (float*)d_out);
}

// round 4
// speedup vs baseline: 2.1807x; 1.2352x over previous
#include <cuda_runtime.h>
#include <math.h>

// GlobalAttentionPooling: per-segment softmax attention readout (single pass).
//   gate = feat @ W (+b, shift-invariant -> dropped)
//   alpha = segment_softmax(gate);  out[b] = sum alpha_n * feat_n
//
// One CTA (4 warps) per segment; each warp owns every 4th node, lane l holds
// dims [4l..4l+3] and [128+4l..] via LDG.128. Per-warp online softmax states,
// merged through smem at the end. Mainloop: 2x unrolled -> 4 LDG.128 in
// flight per warp (MLP=4), interleaved butterflies, streaming (.cs) loads.

#define DD 256
#define MAXB 4096
#define NW 4      // warps per CTA

__device__ int g_seg_start[MAXB + 1];

// Segment start offsets from sorted ids. Handles empty segments and both
// int64/int32 ids via on-device dtype detection: for little-endian int64
// (values < 2^31) the int32 view at odd index n-1 (n even) is a high word = 0;
// sorted int32 data has last id ~ B-1 != 0.
__global__ void seg_bounds_kernel(const int* __restrict__ seg32, int n, int nseg) {
    int stride = (seg32[n - 1] == 0) ? 2 : 1;
    int i = blockIdx.x * blockDim.x + threadIdx.x;
    if (i >= n) return;
    int s  = seg32[(size_t)i * stride];
    int sp = (i == 0) ? -1 : seg32[(size_t)(i - 1) * stride];
    for (int t = sp + 1; t <= s; ++t) g_seg_start[t] = i;
    if (i == n - 1) {
        for (int t = s + 1; t <= nseg; ++t) g_seg_start[t] = n;
    }
}

__device__ __forceinline__ float dot8(const float4& a_lo, const float4& a_hi,
                                      const float4& w_lo, const float4& w_hi) {
    float g;
    g = a_lo.x * w_lo.x;
    g = fmaf(a_lo.y, w_lo.y, g);
    g = fmaf(a_lo.z, w_lo.z, g);
    g = fmaf(a_lo.w, w_lo.w, g);
    g = fmaf(a_hi.x, w_hi.x, g);
    g = fmaf(a_hi.y, w_hi.y, g);
    g = fmaf(a_hi.z, w_hi.z, g);
    g = fmaf(a_hi.w, w_hi.w, g);
    return g;
}

__global__ __launch_bounds__(NW * 32, 7) void pool_kernel(
    const float* __restrict__ feat,
    const float* __restrict__ Wg,
    float* __restrict__ out)
{
    const int b    = blockIdx.x;
    const int tid  = threadIdx.x;
    const int lane = tid & 31;
    const int warp = tid >> 5;

    const int start = g_seg_start[b];
    const int end   = g_seg_start[b + 1];

    if (start >= end) {   // empty segment -> zeros (uniform, before any barrier)
        out[(size_t)b * DD + tid]       = 0.0f;
        out[(size_t)b * DD + tid + 128] = 0.0f;
        return;
    }

    const float4* W4  = (const float4*)Wg;
    const float4 w_lo = W4[lane];
    const float4 w_hi = W4[lane + 32];

    float4 acc_lo = make_float4(0.f, 0.f, 0.f, 0.f);
    float4 acc_hi = make_float4(0.f, 0.f, 0.f, 0.f);
    float  m    = -INFINITY;
    float  ssum = 0.0f;

    int i = start + warp;

    // ---- main loop: 2 nodes per iteration, 4 LDG.128 in flight ----
    for (; i + NW < end; i += 2 * NW) {
        const float4* r0 = (const float4*)(feat + (size_t)i * DD);
        const float4* r1 = (const float4*)(feat + (size_t)(i + NW) * DD);
        const float4 v0_lo = __ldcs(&r0[lane]);
        const float4 v0_hi = __ldcs(&r0[lane + 32]);
        const float4 v1_lo = __ldcs(&r1[lane]);
        const float4 v1_hi = __ldcs(&r1[lane + 32]);

        float g0 = dot8(v0_lo, v0_hi, w_lo, w_hi);
        float g1 = dot8(v1_lo, v1_hi, w_lo, w_hi);
        #pragma unroll
        for (int off = 16; off > 0; off >>= 1) {
            g0 += __shfl_xor_sync(0xffffffffu, g0, off);
            g1 += __shfl_xor_sync(0xffffffffu, g1, off);
        }

        // node 0 update
        if (g0 > m) {
            const float r = __expf(m - g0);
            m = g0;
            ssum = fmaf(ssum, r, 1.0f);
            acc_lo.x = fmaf(acc_lo.x, r, v0_lo.x); acc_lo.y = fmaf(acc_lo.y, r, v0_lo.y);
            acc_lo.z = fmaf(acc_lo.z, r, v0_lo.z); acc_lo.w = fmaf(acc_lo.w, r, v0_lo.w);
            acc_hi.x = fmaf(acc_hi.x, r, v0_hi.x); acc_hi.y = fmaf(acc_hi.y, r, v0_hi.y);
            acc_hi.z = fmaf(acc_hi.z, r, v0_hi.z); acc_hi.w = fmaf(acc_hi.w, r, v0_hi.w);
        } else {
            const float e = __expf(g0 - m);
            ssum += e;
            acc_lo.x = fmaf(e, v0_lo.x, acc_lo.x); acc_lo.y = fmaf(e, v0_lo.y, acc_lo.y);
            acc_lo.z = fmaf(e, v0_lo.z, acc_lo.z); acc_lo.w = fmaf(e, v0_lo.w, acc_lo.w);
            acc_hi.x = fmaf(e, v0_hi.x, acc_hi.x); acc_hi.y = fmaf(e, v0_hi.y, acc_hi.y);
            acc_hi.z = fmaf(e, v0_hi.z, acc_hi.z); acc_hi.w = fmaf(e, v0_hi.w, acc_hi.w);
        }
        // node 1 update
        if (g1 > m) {
            const float r = __expf(m - g1);
            m = g1;
            ssum = fmaf(ssum, r, 1.0f);
            acc_lo.x = fmaf(acc_lo.x, r, v1_lo.x); acc_lo.y = fmaf(acc_lo.y, r, v1_lo.y);
            acc_lo.z = fmaf(acc_lo.z, r, v1_lo.z); acc_lo.w = fmaf(acc_lo.w, r, v1_lo.w);
            acc_hi.x = fmaf(acc_hi.x, r, v1_hi.x); acc_hi.y = fmaf(acc_hi.y, r, v1_hi.y);
            acc_hi.z = fmaf(acc_hi.z, r, v1_hi.z); acc_hi.w = fmaf(acc_hi.w, r, v1_hi.w);
        } else {
            const float e = __expf(g1 - m);
            ssum += e;
            acc_lo.x = fmaf(e, v1_lo.x, acc_lo.x); acc_lo.y = fmaf(e, v1_lo.y, acc_lo.y);
            acc_lo.z = fmaf(e, v1_lo.z, acc_lo.z); acc_lo.w = fmaf(e, v1_lo.w, acc_lo.w);
            acc_hi.x = fmaf(e, v1_hi.x, acc_hi.x); acc_hi.y = fmaf(e, v1_hi.y, acc_hi.y);
            acc_hi.z = fmaf(e, v1_hi.z, acc_hi.z); acc_hi.w = fmaf(e, v1_hi.w, acc_hi.w);
        }
    }

    // ---- remainder: at most one node ----
    if (i < end) {
        const float4* r0 = (const float4*)(feat + (size_t)i * DD);
        const float4 v0_lo = __ldcs(&r0[lane]);
        const float4 v0_hi = __ldcs(&r0[lane + 32]);
        float g0 = dot8(v0_lo, v0_hi, w_lo, w_hi);
        #pragma unroll
        for (int off = 16; off > 0; off >>= 1)
            g0 += __shfl_xor_sync(0xffffffffu, g0, off);
        if (g0 > m) {
            const float r = __expf(m - g0);
            m = g0;
            ssum = fmaf(ssum, r, 1.0f);
            acc_lo.x = fmaf(acc_lo.x, r, v0_lo.x); acc_lo.y = fmaf(acc_lo.y, r, v0_lo.y);
            acc_lo.z = fmaf(acc_lo.z, r, v0_lo.z); acc_lo.w = fmaf(acc_lo.w, r, v0_lo.w);
            acc_hi.x = fmaf(acc_hi.x, r, v0_hi.x); acc_hi.y = fmaf(acc_hi.y, r, v0_hi.y);
            acc_hi.z = fmaf(acc_hi.z, r, v0_hi.z); acc_hi.w = fmaf(acc_hi.w, r, v0_hi.w);
        } else {
            const float e = __expf(g0 - m);
            ssum += e;
            acc_lo.x = fmaf(e, v0_lo.x, acc_lo.x); acc_lo.y = fmaf(e, v0_lo.y, acc_lo.y);
            acc_lo.z = fmaf(e, v0_lo.z, acc_lo.z); acc_lo.w = fmaf(e, v0_lo.w, acc_lo.w);
            acc_hi.x = fmaf(e, v0_hi.x, acc_hi.x); acc_hi.y = fmaf(e, v0_hi.y, acc_hi.y);
            acc_hi.z = fmaf(e, v0_hi.z, acc_hi.z); acc_hi.w = fmaf(e, v0_hi.w, acc_hi.w);
        }
    }

    // ---- merge the NW per-warp softmax states through shared memory ----
    __shared__ float s_m[NW];
    __shared__ float s_s[NW];
    __shared__ float s_acc[NW][DD];

    if (lane == 0) s_m[warp] = m;
    __syncthreads();

    float M = s_m[0];
    #pragma unroll
    for (int wv = 1; wv < NW; ++wv) M = fmaxf(M, s_m[wv]);

    const float scale = __expf(m - M);   // warp with no nodes: m=-inf -> 0
    if (lane == 0) s_s[warp] = ssum * scale;

    float4* sa = (float4*)s_acc[warp];
    acc_lo.x *= scale; acc_lo.y *= scale; acc_lo.z *= scale; acc_lo.w *= scale;
    acc_hi.x *= scale; acc_hi.y *= scale; acc_hi.z *= scale; acc_hi.w *= scale;
    sa[lane]      = acc_lo;
    sa[lane + 32] = acc_hi;
    __syncthreads();

    float tot = s_s[0];
    #pragma unroll
    for (int wv = 1; wv < NW; ++wv) tot += s_s[wv];
    const float inv = 1.0f / tot;

    float o0 = 0.f, o1 = 0.f;
    #pragma unroll
    for (int wv = 0; wv < NW; ++wv) {
        o0 += s_acc[wv][tid];
        o1 += s_acc[wv][tid + 128];
    }
    out[(size_t)b * DD + tid]       = o0 * inv;
    out[(size_t)b * DD + tid + 128] = o1 * inv;
}

extern "C" void kernel_launch(void* const* d_in, const int* in_sizes, int n_in,
                              void* d_out, int out_size) {
    const float* feat  = (const float*)d_in[0];
    const float* Wg    = (const float*)d_in[1];
    const int*   seg32 = (const int*)d_in[3];   // int32 view; dtype detected on device

    const int n = in_sizes[0] / DD;
    int nseg = out_size / DD;
    if (nseg > MAXB) nseg = MAXB;

    seg_bounds_kernel<<<(n + 255) / 256, 256>>>(seg32, n, nseg);
    pool_kernel<<<nseg, NW * 32>>>(feat, Wg, (float*)d_out);
}